// round 5
// baseline (speedup 1.0000x reference)
#include <cuda_runtime.h>

// MaskedConv2D: out = (conv3x3(x, w) + bias) * (maxpool3x3(mask) > 0)
// B=8, CIN=COUT=64, H=W=256, K=3, PAD=1, fp32.
// FFMA2 compute, cp.async double-buffered cin chunks, 16 couts x 8 px / thread.

#define BB   8
#define CC   64
#define HH   256
#define WW   256

#define TH   8       // output rows per block
#define TW   32      // output cols per block
#define NT   128     // threads per block
#define CI_T 8       // cin chunk
#define NCHUNK (CC / CI_T)   // 8
#define XROWS (TH + 2)
#define XCOLS (TW + 2)
#define XSTR  36     // padded smem row stride (floats)

#define SWB (9 * CI_T * 64)          // 4608 floats per weight buffer
#define SXB (CI_T * XROWS * XSTR)    // 2880 floats per x buffer
#define SMB (XROWS * XSTR)           // 360 floats mask tile
#define SMEM_FLOATS (2 * SWB + 2 * SXB + SMB)           // 15336
#define SMEM_BYTES  (SMEM_FLOATS * 4)                   // 61344

// Pre-transposed weights: [chunk][kk][ci][co]
__device__ float g_wtrans[CC * CC * 9];

__global__ void wtrans_kernel(const float* __restrict__ w) {
    int t = blockIdx.x * blockDim.x + threadIdx.x;
    if (t >= CC * CC * 9) return;
    int co = t & 63;
    int r  = t >> 6;            // (chunk*9+kk)*CI_T + ci
    int ci = r & (CI_T - 1);
    int r2 = r >> 3;            // chunk*9 + kk
    int kk = r2 % 9;
    int ch = r2 / 9;
    int ci_g = ch * CI_T + ci;
    g_wtrans[t] = w[co * (CC * 9) + ci_g * 9 + kk];
}

__device__ __forceinline__ unsigned long long pack2(float x, float y) {
    unsigned long long r;
    asm("mov.b64 %0, {%1, %2};" : "=l"(r) : "f"(x), "f"(y));
    return r;
}
__device__ __forceinline__ void fma2(unsigned long long& d,
                                     unsigned long long a,
                                     unsigned long long b) {
    asm("fma.rn.f32x2 %0, %1, %2, %0;" : "+l"(d) : "l"(a), "l"(b));
}
__device__ __forceinline__ float lo32(unsigned long long v) {
    return __uint_as_float((unsigned int)(v & 0xffffffffull));
}
__device__ __forceinline__ float hi32(unsigned long long v) {
    return __uint_as_float((unsigned int)(v >> 32));
}
__device__ __forceinline__ void cpa4(unsigned smem, const float* g) {
    asm volatile("cp.async.ca.shared.global [%0], [%1], 4;"
                 :: "r"(smem), "l"(g));
}
__device__ __forceinline__ void cpa16(unsigned smem, const float* g) {
    asm volatile("cp.async.cg.shared.global [%0], [%1], 16;"
                 :: "r"(smem), "l"(g));
}

__global__ __launch_bounds__(NT, 2)
void masked_conv2d_kernel(const float* __restrict__ x,
                          const float* __restrict__ mask,
                          const float* __restrict__ bias,
                          float* __restrict__ out) {
    extern __shared__ float smem[];
    float* swb[2] = { smem, smem + SWB };
    float* sxb[2] = { smem + 2 * SWB, smem + 2 * SWB + SXB };
    float* sm = smem + 2 * SWB + 2 * SXB;

    const int tid = threadIdx.x;
    const int b  = blockIdx.z;
    const int h0 = blockIdx.y * TH;
    const int w0 = blockIdx.x * TW;

    // warp = one cout group (warp-uniform -> weight LDS is broadcast)
    const int cg  = tid >> 5;         // 0..3
    const int pg  = tid & 31;         // 0..31
    const int lh  = pg >> 2;          // 0..7  output row
    const int lw  = (pg & 3) * 8;     // 0,8,16,24  output col base (8 px/thread)
    const int cob = cg * 16;

    const unsigned smem_base = (unsigned)__cvta_generic_to_shared(smem);
    const unsigned swb_a[2] = { smem_base, smem_base + SWB * 4 };
    const unsigned sxb_a[2] = { smem_base + 2 * SWB * 4,
                                smem_base + (2 * SWB + SXB) * 4 };

    // ---- pre-zero both x buffers (halo cells stay 0 forever) ----
    for (int i = tid; i < 2 * SXB; i += NT)
        sxb[0][i] = 0.f;

    // ---- mask halo tile ----
    for (int i = tid; i < XROWS * XCOLS; i += NT) {
        int r = i / XCOLS, c = i - r * XCOLS;
        int gh = h0 - 1 + r, gw = w0 - 1 + c;
        float v = 0.f;
        if (gh >= 0 && gh < HH && gw >= 0 && gw < WW)
            v = mask[(b * HH + gh) * WW + gw];
        sm[r * XSTR + c] = v;
    }
    __syncthreads();   // zeros + mask visible before any cp.async writes

    // ---- chunk loader: cp.async into buffer bi ----
    auto issue_chunk = [&](int ch, int bi) {
        const float* wsrc = g_wtrans + ch * SWB;
        unsigned wdst = swb_a[bi];
#pragma unroll
        for (int k = 0; k < SWB / 4 / NT; k++) {   // 9 iterations, exact
            int i = tid + k * NT;
            cpa16(wdst + i * 16, wsrc + i * 4);
        }
        for (int i = tid; i < CI_T * XROWS * XCOLS; i += NT) {
            int ci  = i / (XROWS * XCOLS);
            int rem = i - ci * (XROWS * XCOLS);
            int r   = rem / XCOLS;
            int c   = rem - r * XCOLS;
            int gh = h0 - 1 + r, gw = w0 - 1 + c;
            if (gh >= 0 && gh < HH && gw >= 0 && gw < WW)
                cpa4(sxb_a[bi] + ((ci * XROWS + r) * XSTR + c) * 4,
                     x + ((size_t)(b * CC + ch * CI_T + ci) * HH + gh) * WW + gw);
        }
        asm volatile("cp.async.commit_group;");
    };

    // ---- accumulators: 8 pixels x 8 f32x2 (16 couts), init with bias ----
    unsigned long long acc[8][8];
    {
        const float4* bp = (const float4*)(bias + cob);
#pragma unroll
        for (int q = 0; q < 4; q++) {
            float4 bv = bp[q];
            unsigned long long b0 = pack2(bv.x, bv.y);
            unsigned long long b1 = pack2(bv.z, bv.w);
#pragma unroll
            for (int p = 0; p < 8; p++) {
                acc[p][2 * q + 0] = b0;
                acc[p][2 * q + 1] = b1;
            }
        }
    }

    issue_chunk(0, 0);

    for (int ch = 0; ch < NCHUNK; ch++) {
        const int bi = ch & 1;
        if (ch + 1 < NCHUNK) {
            issue_chunk(ch + 1, bi ^ 1);
            asm volatile("cp.async.wait_group 1;");
        } else {
            asm volatile("cp.async.wait_group 0;");
        }
        __syncthreads();

        const float* sw = swb[bi];
        const float* sx = sxb[bi];

#pragma unroll 1
        for (int ci = 0; ci < CI_T; ci++) {
            const float* xb = sx + (ci * XROWS + lh) * XSTR + lw;
#pragma unroll
            for (int kh = 0; kh < 3; kh++) {
                const float* xr = xb + kh * XSTR;
                float4 a0 = *(const float4*)(xr);
                float4 a1 = *(const float4*)(xr + 4);
                float2 a2 = *(const float2*)(xr + 8);
                unsigned long long pk[10];
                pk[0] = pack2(a0.x, a0.x);
                pk[1] = pack2(a0.y, a0.y);
                pk[2] = pack2(a0.z, a0.z);
                pk[3] = pack2(a0.w, a0.w);
                pk[4] = pack2(a1.x, a1.x);
                pk[5] = pack2(a1.y, a1.y);
                pk[6] = pack2(a1.z, a1.z);
                pk[7] = pack2(a1.w, a1.w);
                pk[8] = pack2(a2.x, a2.x);
                pk[9] = pack2(a2.y, a2.y);
#pragma unroll
                for (int kw = 0; kw < 3; kw++) {
                    const ulonglong2* wp = (const ulonglong2*)
                        (sw + ((kh * 3 + kw) * CI_T + ci) * 64 + cob);
#pragma unroll
                    for (int q = 0; q < 4; q++) {
                        ulonglong2 wq2 = wp[q];   // broadcast LDS.128
#pragma unroll
                        for (int p = 0; p < 8; p++) {
                            fma2(acc[p][2 * q + 0], pk[p + kw], wq2.x);
                            fma2(acc[p][2 * q + 1], pk[p + kw], wq2.y);
                        }
                    }
                }
            }
        }
        __syncthreads();
    }

    // ---- validity: 3x3 max-pool of mask tile per pixel ----
    float cm[10];
#pragma unroll
    for (int c = 0; c < 10; c++) {
        float m = 0.f;
#pragma unroll
        for (int dh = 0; dh < 3; dh++)
            m = fmaxf(m, sm[(lh + dh) * XSTR + lw + c]);
        cm[c] = m;
    }
    float vp[8];
#pragma unroll
    for (int p = 0; p < 8; p++) {
        float m = fmaxf(cm[p], fmaxf(cm[p + 1], cm[p + 2]));
        vp[p] = (m > 0.f) ? 1.f : 0.f;
    }

    const int gh = h0 + lh;
    const int gw = w0 + lw;
#pragma unroll
    for (int j = 0; j < 8; j++) {
        float* o0 = out + (((size_t)(b * CC + cob + 2 * j) * HH + gh) * WW + gw);
        float* o1 = o0 + (size_t)HH * WW;
        float4 v0 = make_float4(lo32(acc[0][j]) * vp[0], lo32(acc[1][j]) * vp[1],
                                lo32(acc[2][j]) * vp[2], lo32(acc[3][j]) * vp[3]);
        float4 v1 = make_float4(lo32(acc[4][j]) * vp[4], lo32(acc[5][j]) * vp[5],
                                lo32(acc[6][j]) * vp[6], lo32(acc[7][j]) * vp[7]);
        float4 v2 = make_float4(hi32(acc[0][j]) * vp[0], hi32(acc[1][j]) * vp[1],
                                hi32(acc[2][j]) * vp[2], hi32(acc[3][j]) * vp[3]);
        float4 v3 = make_float4(hi32(acc[4][j]) * vp[4], hi32(acc[5][j]) * vp[5],
                                hi32(acc[6][j]) * vp[6], hi32(acc[7][j]) * vp[7]);
        *(float4*)(o0)     = v0;
        *(float4*)(o0 + 4) = v1;
        *(float4*)(o1)     = v2;
        *(float4*)(o1 + 4) = v3;
    }
}

extern "C" void kernel_launch(void* const* d_in, const int* in_sizes, int n_in,
                              void* d_out, int out_size) {
    const float* x    = (const float*)d_in[0];
    const float* mask = (const float*)d_in[1];
    const float* w    = (const float*)d_in[2];
    const float* bias = (const float*)d_in[3];
    float* out = (float*)d_out;

    wtrans_kernel<<<(CC * CC * 9 + 255) / 256, 256>>>(w);

    cudaFuncSetAttribute(masked_conv2d_kernel,
                         cudaFuncAttributeMaxDynamicSharedMemorySize, SMEM_BYTES);
    dim3 grid(WW / TW, HH / TH, BB);   // (8, 32, 8)
    masked_conv2d_kernel<<<grid, NT, SMEM_BYTES>>>(x, mask, bias, out);
}